// round 16
// baseline (speedup 1.0000x reference)
#include <cuda_runtime.h>
#include <stdint.h>

#define WW 2048
#define STR 8
#define NWW 255
#define P_TOT 32385          /* 127 * 255 */
#define MARGIN_F 1e-4f
#define WARPS_PER_BLK 8
#define NBLOCKS ((P_TOT + WARPS_PER_BLK - 1) / WARPS_PER_BLK)
#define FULL 0xffffffffu

__device__ double   g_loss_sum = 0.0;
__device__ double   g_used     = 0.0;
__device__ unsigned g_done     = 0u;

// bank-conflict-free granule swizzle: 16B granule g -> g ^ ((g>>2)&7)
__device__ __forceinline__ int swz(int g) { return g ^ ((g >> 2) & 7); }

// sel iff sign(dt) != sign(dp): signbit XOR + the dt==0 self-pair case
__device__ __forceinline__ bool sel_pair(float dt, float dp) {
    return (((__float_as_uint(dt) ^ __float_as_uint(dp)) >> 31) != 0u)
           | (dt == 0.0f);
}

// ---------------------------------------------------------------------------
// One warp per patch (8 per block).
//   masked token = (noise_bits & 0xFFFFFF00) | elem_idx   (< 0xFF000000)
//   (unmasked tokens only materialized in the rare path C)
// K = #masked (warp-uniform, ~Bin(256,1/2)):
//   A:  K <= 128          : 128-wide sort of compacted tokens (28 substeps).
//   B': 128 < K <= 160    : sort-128 + direct-descending sort-32 + FOLDED
//                           bitonic merge (pads & known-order exchanges
//                           removed; only rows holding positions < 160 kept).
//   C:  K  > 160 (~3e-5)  : in-register 256-wide sort (36 substeps).
// ---------------------------------------------------------------------------
__global__ void patch_loss_kernel(
    const float* __restrict__ pred,
    const float* __restrict__ target,
    const uint8_t* __restrict__ mask_raw,
    const float* __restrict__ noise,
    float* __restrict__ out)
{
    __shared__ float2   s_pt [WARPS_PER_BLK][256];   // swizzled (pred,target)
    __shared__ uint8_t  s_m  [WARPS_PER_BLK][256];
    __shared__ uint32_t s_tok[WARPS_PER_BLK][256];   // compacted tokens
    __shared__ float    s_blk_loss;
    __shared__ float    s_blk_cnt;
    __shared__ int      s_mode;

    const int wid  = threadIdx.x >> 5;
    const int lane = threadIdx.x & 31;

    if (threadIdx.x == 0) { s_blk_loss = 0.f; s_blk_cnt = 0.f; }
    if (wid == 0) {
        // mask dtype detect on first 1KB (same L2 lines for every block)
        const uint32_t* w = (const uint32_t*)mask_raw;
        uint32_t acc_or = 0; bool gt1 = false;
        #pragma unroll
        for (int i = 0; i < 8; i++) {
            const uint32_t x = __ldg(w + lane + 32 * i);
            acc_or |= x; gt1 |= (x > 1u);
        }
        const unsigned bb = __ballot_sync(FULL, (acc_or & 0xFEFEFEFEu) != 0);
        const unsigned bg = __ballot_sync(FULL, gt1);
        if (lane == 0) s_mode = bb ? 1 : (bg ? 0 : 2);   // f32 : u8 : i32
    }
    __syncthreads();

    const int p = blockIdx.x * WARPS_PER_BLK + wid;
    if (p < P_TOT) {
        const int pi = p / NWW;
        const int pj = p - pi * NWW;
        const int br = pi * STR;
        const int bc = pj * STR;
        const int mode = s_mode;

        const int e0    = lane << 3;             // this thread's 8 elements
        const int a     = lane >> 1;             // patch row
        const int gbase = (br + a) * WW + bc + ((lane & 1) << 3);

        // ---- vectorized loads ----
        const float4 p0 = __ldg((const float4*)(pred + gbase));
        const float4 p1 = __ldg((const float4*)(pred + gbase) + 1);
        const float4 t0 = __ldg((const float4*)(target + gbase));
        const float4 t1 = __ldg((const float4*)(target + gbase) + 1);
        {
            float4* base = (float4*)&s_pt[wid][0];
            const int g0 = lane << 2;
            base[swz(g0 + 0)] = make_float4(p0.x, t0.x, p0.y, t0.y);
            base[swz(g0 + 1)] = make_float4(p0.z, t0.z, p0.w, t0.w);
            base[swz(g0 + 2)] = make_float4(p1.x, t1.x, p1.y, t1.y);
            base[swz(g0 + 3)] = make_float4(p1.z, t1.z, p1.w, t1.w);
        }

        uint32_t mbits;                          // bit r = element e0+r masked
        if (mode == 0) {
            const uint2 mb = __ldg((const uint2*)(mask_raw + gbase));
            uint32_t b = 0;
            #pragma unroll
            for (int r = 0; r < 4; r++) b |= ((mb.x >> (8 * r)) & 1u) << r;
            #pragma unroll
            for (int r = 0; r < 4; r++) b |= ((mb.y >> (8 * r)) & 1u) << (4 + r);
            mbits = b;
        } else if (mode == 1) {
            const float4 m0 = __ldg((const float4*)((const float*)mask_raw + gbase));
            const float4 m1 = __ldg((const float4*)((const float*)mask_raw + gbase) + 1);
            mbits = (m0.x != 0.f) | ((m0.y != 0.f) << 1) | ((m0.z != 0.f) << 2) |
                    ((m0.w != 0.f) << 3) | ((m1.x != 0.f) << 4) | ((m1.y != 0.f) << 5) |
                    ((m1.z != 0.f) << 6) | ((m1.w != 0.f) << 7);
        } else {
            const uint4 m0 = __ldg((const uint4*)((const uint32_t*)mask_raw + gbase));
            const uint4 m1 = __ldg((const uint4*)((const uint32_t*)mask_raw + gbase) + 1);
            mbits = (m0.x != 0) | ((m0.y != 0) << 1) | ((m0.z != 0) << 2) |
                    ((m0.w != 0) << 3) | ((m1.x != 0) << 4) | ((m1.y != 0) << 5) |
                    ((m1.z != 0) << 6) | ((m1.w != 0) << 7);
        }

        const float4 n0 = __ldg((const float4*)(noise + (size_t)p * 256 + e0));
        const float4 n1 = __ldg((const float4*)(noise + (size_t)p * 256 + e0) + 1);

        // masked-form tokens only (unmasked slots are never stored for A/B')
        uint32_t tok[8];
        tok[0] = (__float_as_uint(n0.x) & 0xFFFFFF00u) | (uint32_t)(e0 + 0);
        tok[1] = (__float_as_uint(n0.y) & 0xFFFFFF00u) | (uint32_t)(e0 + 1);
        tok[2] = (__float_as_uint(n0.z) & 0xFFFFFF00u) | (uint32_t)(e0 + 2);
        tok[3] = (__float_as_uint(n0.w) & 0xFFFFFF00u) | (uint32_t)(e0 + 3);
        tok[4] = (__float_as_uint(n1.x) & 0xFFFFFF00u) | (uint32_t)(e0 + 4);
        tok[5] = (__float_as_uint(n1.y) & 0xFFFFFF00u) | (uint32_t)(e0 + 5);
        tok[6] = (__float_as_uint(n1.z) & 0xFFFFFF00u) | (uint32_t)(e0 + 6);
        tok[7] = (__float_as_uint(n1.w) & 0xFFFFFF00u) | (uint32_t)(e0 + 7);

        // ---- ranks of masked elements (element order == 8*lane + r) ----
        const int cnt = __popc(mbits);
        int inc = cnt;
        #pragma unroll
        for (int o = 1; o < 32; o <<= 1) {
            const int t = __shfl_up_sync(FULL, inc, o);
            if (lane >= o) inc += t;
        }
        const int K = __shfl_sync(FULL, inc, 31);   // warp-uniform
        const bool pathA  = (K <= 128);
        const bool pathBp = (K > 128) && (K <= 160);
        const int base = inc - cnt;

        // compaction (independent offsets)
        #pragma unroll
        for (int r = 0; r < 8; r++) {
            if ((mbits >> r) & 1u) {
                const int off = base + __popc(mbits & ((1u << r) - 1u));
                s_m[wid][off]   = (uint8_t)(e0 + r);
                s_tok[wid][off] = tok[r];
            }
        }
        if (pathA) {
            for (int v = K + lane; v < 128; v += 32) s_tok[wid][v] = 0xFFFFFFFFu;
        } else if (pathBp) {
            for (int v = K + lane; v < 160; v += 32) s_tok[wid][v] = 0xFFFFFFFFu;
        }
        __syncwarp();

        const float2* ptbase = &s_pt[wid][0];
        float loss = 0.f;
        int   hit  = 0;

        if (pathA | pathBp) {
            // ==== shared 128-wide sort over positions v = 4*lane + r ====
            uint32_t t4[4];
            {
                const uint4 ld = *(const uint4*)&s_tok[wid][lane << 2];
                t4[0] = ld.x; t4[1] = ld.y; t4[2] = ld.z; t4[3] = ld.w;
            }
            #pragma unroll
            for (int k = 2; k <= 128; k <<= 1) {
                #pragma unroll
                for (int j = k >> 1; j >= 1; j >>= 1) {
                    if (j >= 4) {
                        const int jl = j >> 2;
                        const bool up = ((lane & (k >> 2)) == 0);
                        const bool tm = (up == ((lane & jl) == 0));
                        #pragma unroll
                        for (int r = 0; r < 4; r++) {
                            const uint32_t o = __shfl_xor_sync(FULL, t4[r], jl);
                            t4[r] = tm ? min(t4[r], o) : max(t4[r], o);
                        }
                    } else {
                        #pragma unroll
                        for (int r = 0; r < 4; r++) {
                            if ((r & j) == 0) {
                                const int r2 = r | j;
                                const bool up = (k < 4) ? ((r & k) == 0)
                                                        : ((lane & (k >> 2)) == 0);
                                const uint32_t A = t4[r], B = t4[r2];
                                t4[r]  = up ? min(A, B) : max(A, B);
                                t4[r2] = up ? max(A, B) : min(A, B);
                            }
                        }
                    }
                }
            }

            if (pathA) {
                // ==== epilogue A: 4 positions/thread ====
                #pragma unroll
                for (int r = 0; r < 4; r++) {
                    const int v = (lane << 2) + r;
                    if (v < K) {
                        const int bI = (int)(t4[r] & 0xFFu);
                        const int aI = (int)s_m[wid][v];
                        const float2 A = ptbase[(swz(aI >> 1) << 1) | (aI & 1)];
                        const float2 B = ptbase[(swz(bI >> 1) << 1) | (bI & 1)];
                        const float dt = A.y - B.y;
                        const float dp = A.x - B.x + MARGIN_F;
                        if (sel_pair(dt, dp)) { hit++; loss += fabsf(dp); }
                    }
                }
            } else {
                // ==== B': second half (ranks 128..K-1, <=32 tokens) ====
                // sort DESCENDING directly (mirrored network: min<->max), so
                // pads (0xFFFFFFFF) land first, tokens descending after.
                uint32_t s = s_tok[wid][128 + lane];
                #pragma unroll
                for (int k = 2; k <= 32; k <<= 1) {
                    #pragma unroll
                    for (int j = k >> 1; j >= 1; j >>= 1) {
                        const uint32_t o = __shfl_xor_sync(FULL, s, j);
                        const bool tm = (((lane & k) == 0) == ((lane & j) == 0));
                        s = tm ? max(s, o) : min(s, o);     // mirrored
                    }
                }

                // write sorted-128 back, reload lane-major
                __syncwarp();
                *(uint4*)&s_tok[wid][lane << 2] =
                    make_uint4(t4[0], t4[1], t4[2], t4[3]);
                __syncwarp();

                // lane-major rows; virtual 256 = [asc-128 | pad x3 | desc-32]
                // is bitonic. r-level merge steps folded (pads, a0<a1<a2<a3):
                uint32_t t8[5];
                #pragma unroll
                for (int r = 0; r < 4; r++) t8[r] = s_tok[wid][lane + 32 * r];

                // j=128: only pair (r3, s-row) does work
                const uint32_t n3 = min(t8[3], s);
                const uint32_t n7 = max(t8[3], s);
                // j=64: only pair (r1, n3) does work
                const uint32_t c1 = min(t8[1], n3);
                const uint32_t c3 = max(t8[1], n3);
                // j=32: pairs (r0,c1), (r2,c3); n7 becomes row 4
                t8[1] = max(t8[0], c1);
                t8[0] = min(t8[0], c1);
                t8[3] = max(t8[2], c3);
                t8[2] = min(t8[2], c3);
                t8[4] = n7;

                // j=16..1: intra-row; rows >=5 (positions >=160 >= K) dropped
                #pragma unroll
                for (int j = 16; j >= 1; j >>= 1) {
                    const bool tm = ((lane & j) == 0);
                    #pragma unroll
                    for (int r = 0; r < 5; r++) {
                        const uint32_t o = __shfl_xor_sync(FULL, t8[r], j);
                        t8[r] = tm ? min(t8[r], o) : max(t8[r], o);
                    }
                }

                // ==== epilogue B': positions v = lane+32r, r < 5 ====
                #pragma unroll
                for (int r = 0; r < 5; r++) {
                    const int v = lane + 32 * r;
                    if (v < K) {
                        const int bI = (int)(t8[r] & 0xFFu);
                        const int aI = (int)s_m[wid][v];
                        const float2 A = ptbase[(swz(aI >> 1) << 1) | (aI & 1)];
                        const float2 B = ptbase[(swz(bI >> 1) << 1) | (bI & 1)];
                        const float dt = A.y - B.y;
                        const float dp = A.x - B.x + MARGIN_F;
                        if (sel_pair(dt, dp)) { hit++; loss += fabsf(dp); }
                    }
                }
            }
        } else {
            // ==== path C (K > 160, ~1 patch/run): 256-wide in-register ====
            // reconstruct unmasked sentinel forms (sort last, index kept)
            #pragma unroll
            for (int r = 0; r < 8; r++) {
                if (!((mbits >> r) & 1u))
                    tok[r] = 0xFF000000u | (uint32_t)(e0 + r);
            }
            #pragma unroll
            for (int k = 2; k <= 256; k <<= 1) {
                #pragma unroll
                for (int j = k >> 1; j >= 1; j >>= 1) {
                    if (j >= 8) {
                        const int jl = j >> 3;
                        const bool up = ((lane & (k >> 3)) == 0);
                        const bool tm = (up == ((lane & jl) == 0));
                        #pragma unroll
                        for (int r = 0; r < 8; r++) {
                            const uint32_t o = __shfl_xor_sync(FULL, tok[r], jl);
                            tok[r] = tm ? min(tok[r], o) : max(tok[r], o);
                        }
                    } else {
                        #pragma unroll
                        for (int r = 0; r < 8; r++) {
                            if ((r & j) == 0) {
                                const int r2 = r | j;
                                const bool up = (k < 8) ? ((r & k) == 0)
                                                        : ((lane & (k >> 3)) == 0);
                                const uint32_t A = tok[r], B = tok[r2];
                                tok[r]  = up ? min(A, B) : max(A, B);
                                tok[r2] = up ? max(A, B) : min(A, B);
                            }
                        }
                    }
                }
            }
            #pragma unroll
            for (int r = 0; r < 8; r++) {
                const int v = e0 + r;
                if (v < K) {
                    const int bI = (int)(tok[r] & 0xFFu);
                    const int aI = (int)s_m[wid][v];
                    const float2 A = ptbase[(swz(aI >> 1) << 1) | (aI & 1)];
                    const float2 B = ptbase[(swz(bI >> 1) << 1) | (bI & 1)];
                    const float dt = A.y - B.y;
                    const float dp = A.x - B.x + MARGIN_F;
                    if (sel_pair(dt, dp)) { hit++; loss += fabsf(dp); }
                }
            }
        }

        hit = __reduce_add_sync(FULL, hit);
        #pragma unroll
        for (int o = 16; o; o >>= 1)
            loss += __shfl_xor_sync(FULL, loss, o);
        if (lane == 0 && K > 0) {
            atomicAdd(&s_blk_loss, loss / (float)hit);
            atomicAdd(&s_blk_cnt, 1.0f);
        }
    }
    __syncthreads();

    // ---- block -> global accumulation; last block finalizes + resets ----
    if (threadIdx.x == 0) {
        atomicAdd(&g_loss_sum, (double)s_blk_loss);
        atomicAdd(&g_used,     (double)s_blk_cnt);
        __threadfence();
        const unsigned ticket = atomicAdd(&g_done, 1u);
        if (ticket == (unsigned)(gridDim.x - 1)) {
            const double ls = atomicAdd(&g_loss_sum, 0.0);
            const double us = atomicAdd(&g_used, 0.0);
            out[0] = (float)(ls / us);
            g_loss_sum = 0.0;              // reset for next graph replay
            g_used     = 0.0;
            __threadfence();
            g_done = 0u;
        }
    }
}

// ---------------------------------------------------------------------------
extern "C" void kernel_launch(void* const* d_in, const int* in_sizes, int n_in,
                              void* d_out, int out_size) {
    const float*   pred   = (const float*)d_in[0];
    const float*   target = (const float*)d_in[1];
    const uint8_t* mask   = (const uint8_t*)d_in[2];
    const float*   noise  = (const float*)d_in[3];

    patch_loss_kernel<<<NBLOCKS, 256>>>(pred, target, mask, noise, (float*)d_out);
}